// round 1
// baseline (speedup 1.0000x reference)
#include <cuda_runtime.h>
#include <math.h>

#define FEA     512
#define FEA4    (4*FEA)          // 2048
#define LAB_BOS 402
#define L_OBS   100
#define KP1     21
#define NROW1   (L_OBS*FEA)      // 51200

#define B1   400                 // blocks for big W_all GEMV
#define R1   (NROW1/B1)          // 128 rows per block
#define B1C  16                  // second-level partial chunks
#define B1PER (B1/B1C)           // 25

#define B2   24                  // W3   (1536 rows)
#define R2   64
#define B3   16                  // W_eh (1024 rows)
#define R3   64
#define B4   16                  // W_lin pass 1 (1024 rows)
#define R4   64
#define B5   16                  // W_lin pass 2 (1024 rows)
#define R5   64
#define B6   16                  // W_ih|W_hh (2x512 rows), OUT=2048
#define R6   64
#define B7   16                  // W_out (512 rows), OUT=402
#define R7   32

// ---------------- scratch (device globals: allocation-free) ----------------
__device__ __align__(16) float g_P1 [B1*FEA];     // emb1 partials (level 1)
__device__ __align__(16) float g_P1b[B1C*FEA];    // emb1 partials (level 2)
__device__ __align__(16) float g_Pemb[B2*FEA];    // emb partials
__device__ __align__(16) float g_Pinp[B3*FEA];    // inp partials
__device__ __align__(16) float g_Papp[B4*FEA];    // app partials
__device__ __align__(16) float g_Px  [B5*FEA];    // x (pre-relu) partials
__device__ __align__(16) float g_Pg  [B6*FEA4];   // gates partials
__device__ __align__(16) float g_Plg [B7*LAB_BOS];// logits partials

// ---------------- helpers ----------------
// Partial GEMV: 128 threads, OUT=512, thread t owns cols 4t..4t+3 (float4).
__device__ __forceinline__ void gemv_part512(const float* __restrict__ xs,
                                             const float* __restrict__ Wbase,
                                             int R, float* __restrict__ Pout) {
    int t = threadIdx.x;
    float4 acc = make_float4(0.f, 0.f, 0.f, 0.f);
    const float* Wp = Wbase + 4*t;
#pragma unroll 4
    for (int r = 0; r < R; r++) {
        float4 w = *(const float4*)(Wp + (size_t)r*FEA);
        float xv = xs[r];
        acc.x = fmaf(xv, w.x, acc.x);
        acc.y = fmaf(xv, w.y, acc.y);
        acc.z = fmaf(xv, w.z, acc.z);
        acc.w = fmaf(xv, w.w, acc.w);
    }
    *(float4*)(Pout + 4*t) = acc;
}

// Reduce NB partial rows of width 512 (+bias) into smem, threads=128.
template<int NB>
__device__ __forceinline__ void reduce512(const float* __restrict__ P,
                                          const float* __restrict__ bias,
                                          float* __restrict__ out) {
    int t = threadIdx.x;
#pragma unroll
    for (int k = 0; k < 4; k++) {
        int j = t + 128*k;
        float s = bias[j];
#pragma unroll
        for (int b = 0; b < NB; b++) s += P[b*FEA + j];
        out[j] = s;
    }
}

__device__ __forceinline__ float sigmf(float v) { return 1.f / (1.f + expf(-v)); }

// ---------------- K1: emb1 big GEMV partials (104.9 MB of W_all) ----------------
__global__ void k_emb1(const int* __restrict__ lab_value,
                       const float* __restrict__ lab_table,
                       const float* __restrict__ W_all) {
    __shared__ float xs[R1];
    int t = threadIdx.x;                 // 128
    int base = blockIdx.x * R1;
    for (int r = t; r < R1; r += 128) {
        int row = base + r;
        int l = row >> 9, f = row & 511;
        int id = 2*l + 1 - lab_value[l];     // value==1 -> even row, else odd
        xs[r] = lab_table[(size_t)id*FEA + f];
    }
    __syncthreads();
    gemv_part512(xs, W_all + (size_t)base*FEA, R1, g_P1 + (size_t)blockIdx.x*FEA);
}

// K1.5: 2-level reduce of the 400 partials down to 16 (avoids L2-latency-bound 400-deep serial sums)
__global__ void k_red1() {
    int t  = threadIdx.x;                // 128
    int jb = blockIdx.x & 3;
    int bc = blockIdx.x >> 2;            // 0..15
    int j  = jb*128 + t;
    float s = 0.f;
#pragma unroll 5
    for (int b = bc*B1PER; b < (bc+1)*B1PER; b++) s += g_P1[b*FEA + j];
    g_P1b[bc*FEA + j] = s;
}

// ---------------- K2: emb = [emb1, a*e2, (1-a)*e3] @ W3 + b3 (partials) ----------------
__global__ void k_emb(const int* __restrict__ pindex, const float* __restrict__ palpha,
                      const float* __restrict__ lab_table,
                      const float* __restrict__ b_all, const float* __restrict__ W3) {
    __shared__ float xs[3*FEA];
    reduce512<B1C>(g_P1b, b_all, xs);                // emb1
    int t = threadIdx.x;
    int index = pindex[0];
    float alpha = palpha[0];
    const float* e2 = lab_table + (size_t)(index + 2)*FEA;
    const float* e3 = lab_table + (size_t)(index + 3)*FEA;
#pragma unroll
    for (int k = 0; k < 4; k++) {
        int j = t + 128*k;
        xs[FEA   + j] = e2[j] * alpha;
        xs[2*FEA + j] = e3[j] * (1.f - alpha);
    }
    __syncthreads();
    int base = blockIdx.x * R2;
    gemv_part512(xs + base, W3 + (size_t)base*FEA, R2, g_Pemb + (size_t)blockIdx.x*FEA);
}

// ---------------- K3: inp = [emb, h0] @ W_eh + b_eh (partials) ----------------
__global__ void k_inp(const float* __restrict__ b3, const float* __restrict__ h0,
                      const float* __restrict__ W_eh) {
    __shared__ float xs[2*FEA];
    reduce512<B2>(g_Pemb, b3, xs);                   // emb
    int t = threadIdx.x;
#pragma unroll
    for (int k = 0; k < 4; k++) xs[FEA + t + 128*k] = h0[t + 128*k];
    __syncthreads();
    int base = blockIdx.x * R3;
    gemv_part512(xs + base, W_eh + (size_t)base*FEA, R3, g_Pinp + (size_t)blockIdx.x*FEA);
}

// ---------------- K4: aw -> ctx -> app = ctx @ W_lin + b_lin (partials) ----------------
__global__ void k_app(const float* __restrict__ b_eh,
                      const float* __restrict__ W_aw, const float* __restrict__ b_aw,
                      const float* __restrict__ enc,  const float* __restrict__ W_lin) {
    __shared__ float inp[FEA];
    __shared__ float aw4[4][24];
    __shared__ float aw[24];
    __shared__ float ctx[2*FEA];
    reduce512<B3>(g_Pinp, b_eh, inp);
    __syncthreads();
    int t = threadIdx.x, w = t >> 5, lane = t & 31;
    if (lane < KP1) {                                  // aw = inp @ W_aw, split over 4 warps
        float a = 0.f;
        int i0 = w * 128;
#pragma unroll 8
        for (int i = 0; i < 128; i++)
            a = fmaf(inp[i0 + i], W_aw[(size_t)(i0 + i)*KP1 + lane], a);
        aw4[w][lane] = a;
    }
    __syncthreads();
    if (t < KP1) aw[t] = b_aw[t] + aw4[0][t] + aw4[1][t] + aw4[2][t] + aw4[3][t];
    __syncthreads();
#pragma unroll
    for (int k = 0; k < 8; k++) {                      // ctx = aw @ enc[0]  [1024]
        int d = t + 128*k;
        float s = 0.f;
#pragma unroll
        for (int o = 0; o < KP1; o++) s = fmaf(aw[o], enc[o*(2*FEA) + d], s);
        ctx[d] = s;
    }
    __syncthreads();
    int base = blockIdx.x * R4;
    gemv_part512(ctx + base, W_lin + (size_t)base*FEA, R4, g_Papp + (size_t)blockIdx.x*FEA);
}

// ---------------- K5: x_pre = [emb, app] @ W_lin + b_lin (partials; relu at consumer) ----------------
__global__ void k_x(const float* __restrict__ b3, const float* __restrict__ b_lin,
                    const float* __restrict__ W_lin) {
    __shared__ float xs[2*FEA];
    reduce512<B2>(g_Pemb, b3,    xs);        // emb (re-reduced, cheap L2)
    reduce512<B4>(g_Papp, b_lin, xs + FEA);  // app
    __syncthreads();
    int base = blockIdx.x * R5;
    gemv_part512(xs + base, W_lin + (size_t)base*FEA, R5, g_Px + (size_t)blockIdx.x*FEA);
}

// ---------------- K6: gates partials. blocks 0..7: relu(x)@W_ih ; blocks 8..15: h0@W_hh ----------------
__global__ void k_gates(const float* __restrict__ b_lin, const float* __restrict__ h0,
                        const float* __restrict__ W_ih, const float* __restrict__ W_hh) {
    __shared__ float xs[FEA];
    int t = threadIdx.x;                     // 512
    bool isH = blockIdx.x >= 8;
    if (!isH) {
        float s = b_lin[t];
#pragma unroll
        for (int b = 0; b < B5; b++) s += g_Px[b*FEA + t];
        xs[t] = fmaxf(s, 0.f);               // relu
    } else {
        xs[t] = h0[t];
    }
    __syncthreads();
    int rbase = (blockIdx.x & 7) * R6;
    const float* W = (isH ? W_hh : W_ih) + (size_t)rbase*FEA4 + 4*t;
    float4 acc = make_float4(0.f, 0.f, 0.f, 0.f);
#pragma unroll 4
    for (int r = 0; r < R6; r++) {
        float4 w = *(const float4*)(W + (size_t)r*FEA4);
        float xv = xs[rbase + r];
        acc.x = fmaf(xv, w.x, acc.x);
        acc.y = fmaf(xv, w.y, acc.y);
        acc.z = fmaf(xv, w.z, acc.z);
        acc.w = fmaf(xv, w.w, acc.w);
    }
    *(float4*)(g_Pg + (size_t)blockIdx.x*FEA4 + 4*t) = acc;
}

// ---------------- K7: h_new -> logits partials ----------------
__global__ void k_logits(const float* __restrict__ b_ih, const float* __restrict__ b_hh,
                         const float* __restrict__ c0,   const float* __restrict__ W_out) {
    __shared__ float gsum[FEA4];
    __shared__ float hnew[FEA];
    int t = threadIdx.x;                     // 128
#pragma unroll
    for (int k = 0; k < 16; k++) {
        int j = t + 128*k;
        float s = b_ih[j] + b_hh[j];
#pragma unroll
        for (int b = 0; b < B6; b++) s += g_Pg[b*FEA4 + j];
        gsum[j] = s;
    }
    __syncthreads();
#pragma unroll
    for (int k = 0; k < 4; k++) {
        int j = t + 128*k;
        float si = sigmf(gsum[j]);
        float sf = sigmf(gsum[FEA + j]);
        float so = sigmf(gsum[3*FEA + j]);
        float cn = sf * c0[j] + si * tanhf(gsum[2*FEA + j]);
        hnew[j] = so * tanhf(cn);
    }
    __syncthreads();
    int base = blockIdx.x * R7;
    float acc[4] = {0.f, 0.f, 0.f, 0.f};
    for (int r = 0; r < R7; r++) {
        float xv = hnew[base + r];
        const float* Wp = W_out + (size_t)(base + r)*LAB_BOS;
#pragma unroll
        for (int k = 0; k < 4; k++) {
            int j = t + 128*k;
            if (j < LAB_BOS) acc[k] = fmaf(xv, Wp[j], acc[k]);
        }
    }
#pragma unroll
    for (int k = 0; k < 4; k++) {
        int j = t + 128*k;
        if (j < LAB_BOS) g_Plg[blockIdx.x*LAB_BOS + j] = acc[k];
    }
}

// ---------------- K8: final — log_softmax + LSTM state outputs ----------------
__global__ void k_final(const float* __restrict__ b_ih, const float* __restrict__ b_hh,
                        const float* __restrict__ b_out, const float* __restrict__ c0,
                        float* __restrict__ out) {
    __shared__ float gsum[FEA4];
    __shared__ float logits[LAB_BOS];
    __shared__ float red[512];
    int t = threadIdx.x;                     // 512
#pragma unroll
    for (int k = 0; k < 4; k++) {
        int j = t + 512*k;
        float s = b_ih[j] + b_hh[j];
#pragma unroll
        for (int b = 0; b < B6; b++) s += g_Pg[b*FEA4 + j];
        gsum[j] = s;
    }
    if (t < LAB_BOS) {
        float s = b_out[t];
#pragma unroll
        for (int b = 0; b < B7; b++) s += g_Plg[b*LAB_BOS + t];
        logits[t] = s;
    }
    __syncthreads();
    {   // LSTM elementwise (torch gate order i,f,g,o); write h_new / c_new
        float si = sigmf(gsum[t]);
        float sf = sigmf(gsum[FEA + t]);
        float so = sigmf(gsum[3*FEA + t]);
        float cn = sf * c0[t] + si * tanhf(gsum[2*FEA + t]);
        float hn = so * tanhf(cn);
        out[LAB_BOS + t]       = hn;   // h_new at [402, 914)
        out[LAB_BOS + FEA + t] = cn;   // c_new at [914, 1426)
    }
    // log_softmax over 402 logits
    red[t] = (t < LAB_BOS) ? logits[t] : -INFINITY;
    __syncthreads();
    for (int s = 256; s > 0; s >>= 1) {
        if (t < s) red[t] = fmaxf(red[t], red[t + s]);
        __syncthreads();
    }
    float m = red[0];
    __syncthreads();
    red[t] = (t < LAB_BOS) ? expf(logits[t] - m) : 0.f;
    __syncthreads();
    for (int s = 256; s > 0; s >>= 1) {
        if (t < s) red[t] += red[t + s];
        __syncthreads();
    }
    float lse = logf(red[0]) + m;
    if (t < LAB_BOS) out[t] = logits[t] - lse;
}

// ---------------- launch ----------------
extern "C" void kernel_launch(void* const* d_in, const int* in_sizes, int n_in,
                              void* d_out, int out_size) {
    (void)in_sizes; (void)n_in; (void)out_size;
    const int*   index     = (const int*)  d_in[0];
    const int*   lab_value = (const int*)  d_in[1];
    const float* alpha     = (const float*)d_in[2];
    const float* h0        = (const float*)d_in[3];
    const float* c0        = (const float*)d_in[4];
    const float* enc       = (const float*)d_in[5];
    const float* lab_table = (const float*)d_in[6];
    const float* W_all     = (const float*)d_in[7];
    const float* b_all     = (const float*)d_in[8];
    const float* W3        = (const float*)d_in[9];
    const float* b3        = (const float*)d_in[10];
    const float* W_eh      = (const float*)d_in[11];
    const float* b_eh      = (const float*)d_in[12];
    const float* W_aw      = (const float*)d_in[13];
    const float* b_aw      = (const float*)d_in[14];
    const float* W_lin     = (const float*)d_in[15];
    const float* b_lin     = (const float*)d_in[16];
    const float* W_ih      = (const float*)d_in[17];
    const float* W_hh      = (const float*)d_in[18];
    const float* b_ih      = (const float*)d_in[19];
    const float* b_hh      = (const float*)d_in[20];
    const float* W_out     = (const float*)d_in[21];
    const float* b_out     = (const float*)d_in[22];
    float* out = (float*)d_out;

    k_emb1  <<<B1, 128>>>(lab_value, lab_table, W_all);
    k_red1  <<<64, 128>>>();
    k_emb   <<<B2, 128>>>(index, alpha, lab_table, b_all, W3);
    k_inp   <<<B3, 128>>>(b3, h0, W_eh);
    k_app   <<<B4, 128>>>(b_eh, W_aw, b_aw, enc, W_lin);
    k_x     <<<B5, 128>>>(b3, b_lin, W_lin);
    k_gates <<<B6, 512>>>(b_lin, h0, W_ih, W_hh);
    k_logits<<<B7, 128>>>(b_ih, b_hh, c0, W_out);
    k_final <<<1, 512>>>(b_ih, b_hh, b_out, c0, out);
}

// round 4
// speedup vs baseline: 1.5085x; 1.5085x over previous
#include <cuda_runtime.h>
#include <math.h>

#define FEA     512
#define FEA4    (4*FEA)          // 2048
#define LAB_BOS 402
#define L_OBS   100
#define KP1     21
#define NROW1   (L_OBS*FEA)      // 51200

#define B1    400                // blocks for big W_all GEMV
#define R1    (NROW1/B1)         // 128 rows per block
#define B1C   16                 // second-level partial chunks
#define B1PER (B1/B1C)           // 25

#define B_EMB   96               // W3: 1536 rows, 16 rows/block
#define R_EMB   16
#define B_INP   32               // W_eh: 1024 rows, 32 rows/block
#define R_INP   32
#define B_APP   32               // W_lin pass1
#define R_APP   32
#define B_X     32               // W_lin pass2
#define R_X     32
#define B_G     16               // row chunks for W_ih / W_hh (32 rows each)
#define R_G     32
#define B_LG    16               // W_out: 512 rows, 32 rows/block
#define R_LG    32

// ---------------- scratch (device globals: allocation-free) ----------------
__device__ __align__(16) float g_P1  [B1*FEA];
__device__ __align__(16) float g_P1b [B1C*FEA];
__device__ __align__(16) float g_Pemb[B_EMB*FEA];
__device__ __align__(16) float g_emb [FEA];
__device__ __align__(16) float g_Pinp[B_INP*FEA];
__device__ __align__(16) float g_ctx [2*FEA];
__device__ __align__(16) float g_Papp[B_APP*FEA];
__device__ __align__(16) float g_Px  [B_X*FEA];
__device__ __align__(16) float g_Pgi [B_G*FEA4];
__device__ __align__(16) float g_Pgh [B_G*FEA4];
__device__ __align__(16) float g_Plg [B_LG*LAB_BOS];

__device__ __forceinline__ float sigmf(float v) { return 1.f / (1.f + expf(-v)); }

// ---------------- K1: blocks [0,400): W_all GEMV partials (104.9 MB stream)
//                      blocks [400,416): h0 @ W_hh partials (4 MB, h0-only dep, hidden under the big stream)
__global__ void k_emb1(const int* __restrict__ lab_value,
                       const float* __restrict__ lab_table,
                       const float* __restrict__ W_all,
                       const float* __restrict__ h0,
                       const float* __restrict__ W_hh) {
    __shared__ float xs[R1];
    int t = threadIdx.x;                 // 128
    if (blockIdx.x < B1) {
        int base = blockIdx.x * R1;
        {
            int row = base + t;          // R1 == blockDim.x == 128
            int l = row >> 9, f = row & 511;
            int id = 2*l + 1 - lab_value[l];
            xs[t] = lab_table[(size_t)id*FEA + f];
        }
        __syncthreads();
        float4 acc = make_float4(0.f, 0.f, 0.f, 0.f);
        const float* Wp = W_all + (size_t)base*FEA + 4*t;
#pragma unroll 8
        for (int r = 0; r < R1; r++) {
            float4 w = *(const float4*)(Wp + (size_t)r*FEA);
            float xv = xs[r];
            acc.x = fmaf(xv, w.x, acc.x);
            acc.y = fmaf(xv, w.y, acc.y);
            acc.z = fmaf(xv, w.z, acc.z);
            acc.w = fmaf(xv, w.w, acc.w);
        }
        *(float4*)(g_P1 + (size_t)blockIdx.x*FEA + 4*t) = acc;
    } else {
        // h0 @ W_hh : rchunk covers 32 rows; thread t owns cols {4t..4t+3} of each 512-col quarter
        int rchunk = blockIdx.x - B1;    // 0..15
        int base = rchunk * R_G;
        if (t < R_G) xs[t] = h0[base + t];
        __syncthreads();
        float4 acc[4];
#pragma unroll
        for (int q = 0; q < 4; q++) acc[q] = make_float4(0.f, 0.f, 0.f, 0.f);
        const float* Wp = W_hh + (size_t)base*FEA4 + 4*t;
#pragma unroll
        for (int r = 0; r < R_G; r++) {
            float xv = xs[r];
#pragma unroll
            for (int q = 0; q < 4; q++) {
                float4 w = *(const float4*)(Wp + (size_t)r*FEA4 + 512*q);
                acc[q].x = fmaf(xv, w.x, acc[q].x);
                acc[q].y = fmaf(xv, w.y, acc[q].y);
                acc[q].z = fmaf(xv, w.z, acc[q].z);
                acc[q].w = fmaf(xv, w.w, acc[q].w);
            }
        }
#pragma unroll
        for (int q = 0; q < 4; q++)
            *(float4*)(g_Pgh + (size_t)rchunk*FEA4 + 4*t + 512*q) = acc[q];
    }
}

// K2: reduce 400 partials -> 16
__global__ void k_red1() {
    int t  = threadIdx.x;                // 128
    int jb = blockIdx.x & 3;
    int bc = blockIdx.x >> 2;            // 0..15
    int j  = jb*128 + t;
    float s = 0.f;
#pragma unroll 5
    for (int b = bc*B1PER; b < (bc+1)*B1PER; b++) s += g_P1[b*FEA + j];
    g_P1b[bc*FEA + j] = s;
}

// ---------------- K3: emb = [emb1, a*e2, (1-a)*e3] @ W3 (partials) ----------------
__global__ void k_emb(const int* __restrict__ pindex, const float* __restrict__ palpha,
                      const float* __restrict__ lab_table,
                      const float* __restrict__ b_all, const float* __restrict__ W3) {
    __shared__ float xs[R_EMB];
    int t = threadIdx.x;                 // 128
    int base = blockIdx.x * R_EMB;
    if (t < R_EMB) {
        int row = base + t;
        float v;
        if (row < FEA) {
            v = b_all[row];
#pragma unroll
            for (int b = 0; b < B1C; b++) v += g_P1b[b*FEA + row];
        } else if (row < 2*FEA) {
            v = lab_table[(size_t)(pindex[0] + 2)*FEA + (row - FEA)] * palpha[0];
        } else {
            v = lab_table[(size_t)(pindex[0] + 3)*FEA + (row - 2*FEA)] * (1.f - palpha[0]);
        }
        xs[t] = v;
    }
    __syncthreads();
    float4 acc = make_float4(0.f, 0.f, 0.f, 0.f);
    const float* Wp = W3 + (size_t)base*FEA + 4*t;
#pragma unroll
    for (int r = 0; r < R_EMB; r++) {
        float4 w = *(const float4*)(Wp + (size_t)r*FEA);
        float xv = xs[r];
        acc.x = fmaf(xv, w.x, acc.x);
        acc.y = fmaf(xv, w.y, acc.y);
        acc.z = fmaf(xv, w.z, acc.z);
        acc.w = fmaf(xv, w.w, acc.w);
    }
    *(float4*)(g_Pemb + (size_t)blockIdx.x*FEA + 4*t) = acc;
}

// K4: combine emb partials -> g_emb (with b3)
__global__ void k_vec_emb(const float* __restrict__ b3) {
    int j = blockIdx.x*128 + threadIdx.x;     // 4 blocks x 128
    float s = b3[j];
#pragma unroll 8
    for (int b = 0; b < B_EMB; b++) s += g_Pemb[b*FEA + j];
    g_emb[j] = s;
}

// ---------------- K5: inp = [emb, h0] @ W_eh (partials) ----------------
__global__ void k_inp(const float* __restrict__ h0, const float* __restrict__ W_eh) {
    __shared__ float xs[R_INP];
    int t = threadIdx.x;                 // 128
    int base = blockIdx.x * R_INP;
    if (t < R_INP) {
        int row = base + t;
        xs[t] = (row < FEA) ? g_emb[row] : h0[row - FEA];
    }
    __syncthreads();
    float4 acc = make_float4(0.f, 0.f, 0.f, 0.f);
    const float* Wp = W_eh + (size_t)base*FEA + 4*t;
#pragma unroll
    for (int r = 0; r < R_INP; r++) {
        float4 w = *(const float4*)(Wp + (size_t)r*FEA);
        float xv = xs[r];
        acc.x = fmaf(xv, w.x, acc.x);
        acc.y = fmaf(xv, w.y, acc.y);
        acc.z = fmaf(xv, w.z, acc.z);
        acc.w = fmaf(xv, w.w, acc.w);
    }
    *(float4*)(g_Pinp + (size_t)blockIdx.x*FEA + 4*t) = acc;
}

// ---------------- K6: attention: inp -> aw -> ctx ----------------
__global__ void k_attn(const float* __restrict__ b_eh,
                       const float* __restrict__ W_aw, const float* __restrict__ b_aw,
                       const float* __restrict__ enc) {
    __shared__ float inp[FEA];
    __shared__ float awp[16][32];
    __shared__ float aw[KP1+3];
    int t = threadIdx.x;                 // 512
    {
        float s = b_eh[t];
#pragma unroll 8
        for (int b = 0; b < B_INP; b++) s += g_Pinp[b*FEA + t];
        inp[t] = s;
    }
    __syncthreads();
    int w = t >> 5, lane = t & 31;
    if (lane < KP1) {                    // 16 warps x 32 input rows each
        float a = 0.f;
        int i0 = w * 32;
#pragma unroll
        for (int i = 0; i < 32; i++)
            a = fmaf(inp[i0 + i], W_aw[(size_t)(i0 + i)*KP1 + lane], a);
        awp[w][lane] = a;
    }
    __syncthreads();
    if (t < KP1) {
        float s = b_aw[t];
#pragma unroll
        for (int ww = 0; ww < 16; ww++) s += awp[ww][t];
        aw[t] = s;
    }
    __syncthreads();
#pragma unroll
    for (int k = 0; k < 2; k++) {        // ctx = aw @ enc[0]  (1024 wide)
        int d = t + 512*k;
        float s = 0.f;
#pragma unroll
        for (int o = 0; o < KP1; o++) s = fmaf(aw[o], enc[o*(2*FEA) + d], s);
        g_ctx[d] = s;
    }
}

// ---------------- K7: app = ctx @ W_lin (partials) ----------------
__global__ void k_app(const float* __restrict__ W_lin) {
    __shared__ float xs[R_APP];
    int t = threadIdx.x;                 // 128
    int base = blockIdx.x * R_APP;
    if (t < R_APP) xs[t] = g_ctx[base + t];
    __syncthreads();
    float4 acc = make_float4(0.f, 0.f, 0.f, 0.f);
    const float* Wp = W_lin + (size_t)base*FEA + 4*t;
#pragma unroll
    for (int r = 0; r < R_APP; r++) {
        float4 w = *(const float4*)(Wp + (size_t)r*FEA);
        float xv = xs[r];
        acc.x = fmaf(xv, w.x, acc.x);
        acc.y = fmaf(xv, w.y, acc.y);
        acc.z = fmaf(xv, w.z, acc.z);
        acc.w = fmaf(xv, w.w, acc.w);
    }
    *(float4*)(g_Papp + (size_t)blockIdx.x*FEA + 4*t) = acc;
}

// ---------------- K8: x_pre = [emb, app] @ W_lin (partials) ----------------
__global__ void k_x(const float* __restrict__ b_lin, const float* __restrict__ W_lin) {
    __shared__ float xs[R_X];
    int t = threadIdx.x;                 // 128
    int base = blockIdx.x * R_X;
    if (t < R_X) {
        int row = base + t;
        float v;
        if (row < FEA) {
            v = g_emb[row];
        } else {
            int j = row - FEA;
            v = b_lin[j];
#pragma unroll
            for (int b = 0; b < B_APP; b++) v += g_Papp[b*FEA + j];
        }
        xs[t] = v;
    }
    __syncthreads();
    float4 acc = make_float4(0.f, 0.f, 0.f, 0.f);
    const float* Wp = W_lin + (size_t)base*FEA + 4*t;
#pragma unroll
    for (int r = 0; r < R_X; r++) {
        float4 w = *(const float4*)(Wp + (size_t)r*FEA);
        float xv = xs[r];
        acc.x = fmaf(xv, w.x, acc.x);
        acc.y = fmaf(xv, w.y, acc.y);
        acc.z = fmaf(xv, w.z, acc.z);
        acc.w = fmaf(xv, w.w, acc.w);
    }
    *(float4*)(g_Px + (size_t)blockIdx.x*FEA + 4*t) = acc;
}

// ---------------- K9: gates partials, W_ih only (W_hh handled in K1) ----------------
__global__ void k_gates(const float* __restrict__ b_lin, const float* __restrict__ W_ih) {
    __shared__ float xs[R_G];
    int t = threadIdx.x;                 // 512
    int base = blockIdx.x * R_G;
    if (t < R_G) {
        int row = base + t;
        float s = b_lin[row];
#pragma unroll
        for (int b = 0; b < B_X; b++) s += g_Px[b*FEA + row];
        xs[t] = fmaxf(s, 0.f);           // relu
    }
    __syncthreads();
    const float* W = W_ih + (size_t)base*FEA4 + 4*t;
    float4 acc = make_float4(0.f, 0.f, 0.f, 0.f);
#pragma unroll
    for (int r = 0; r < R_G; r++) {
        float4 w = *(const float4*)(W + (size_t)r*FEA4);
        float xv = xs[r];
        acc.x = fmaf(xv, w.x, acc.x);
        acc.y = fmaf(xv, w.y, acc.y);
        acc.z = fmaf(xv, w.z, acc.z);
        acc.w = fmaf(xv, w.w, acc.w);
    }
    *(float4*)(g_Pgi + (size_t)blockIdx.x*FEA4 + 4*t) = acc;
}

// ---------------- K10: hnew slice + logits partials; writes h_new/c_new directly ----------------
__global__ void k_logits(const float* __restrict__ b_ih, const float* __restrict__ b_hh,
                         const float* __restrict__ c0,   const float* __restrict__ W_out,
                         float* __restrict__ out) {
    __shared__ float gg[128];            // interleaved: t = 4*r + gate
    __shared__ float hn_s[R_LG];
    int t = threadIdx.x;                 // 128
    int base = blockIdx.x * R_LG;        // rows of hnew / W_out
    {
        int r = base + (t >> 2);
        int gate = t & 3;
        int j = gate*FEA + r;
        float s = b_ih[j] + b_hh[j];
#pragma unroll
        for (int b = 0; b < B_G; b++) s += g_Pgi[b*FEA4 + j];
#pragma unroll
        for (int b = 0; b < B_G; b++) s += g_Pgh[b*FEA4 + j];
        gg[t] = s;
    }
    __syncthreads();
    if (t < R_LG) {
        int r = base + t;
        float si = sigmf(gg[4*t + 0]);
        float sf = sigmf(gg[4*t + 1]);
        float gv = tanhf(gg[4*t + 2]);
        float so = sigmf(gg[4*t + 3]);
        float cn = sf * c0[r] + si * gv;
        float hn = so * tanhf(cn);
        hn_s[t] = hn;
        out[LAB_BOS + r]       = hn;     // h_new
        out[LAB_BOS + FEA + r] = cn;     // c_new
    }
    __syncthreads();
    float acc[4] = {0.f, 0.f, 0.f, 0.f};
#pragma unroll
    for (int r = 0; r < R_LG; r++) {
        float xv = hn_s[r];
        const float* Wp = W_out + (size_t)(base + r)*LAB_BOS;
#pragma unroll
        for (int k = 0; k < 4; k++) {
            int j = t + 128*k;
            if (j < LAB_BOS) acc[k] = fmaf(xv, Wp[j], acc[k]);
        }
    }
#pragma unroll
    for (int k = 0; k < 4; k++) {
        int j = t + 128*k;
        if (j < LAB_BOS) g_Plg[blockIdx.x*LAB_BOS + j] = acc[k];
    }
}

// ---------------- K11: final log_softmax ----------------
__global__ void k_final(const float* __restrict__ b_out, float* __restrict__ out) {
    __shared__ float logits[LAB_BOS];
    __shared__ float red[512];
    int t = threadIdx.x;                 // 512
    if (t < LAB_BOS) {
        float s = b_out[t];
#pragma unroll
        for (int b = 0; b < B_LG; b++) s += g_Plg[b*LAB_BOS + t];
        logits[t] = s;
    }
    __syncthreads();
    red[t] = (t < LAB_BOS) ? logits[t] : -INFINITY;
    __syncthreads();
    for (int s = 256; s > 0; s >>= 1) {
        if (t < s) red[t] = fmaxf(red[t], red[t + s]);
        __syncthreads();
    }
    float m = red[0];
    __syncthreads();
    red[t] = (t < LAB_BOS) ? expf(logits[t] - m) : 0.f;
    __syncthreads();
    for (int s = 256; s > 0; s >>= 1) {
        if (t < s) red[t] += red[t + s];
        __syncthreads();
    }
    float lse = logf(red[0]) + m;
    if (t < LAB_BOS) out[t] = logits[t] - lse;
}

// ---------------- launch ----------------
extern "C" void kernel_launch(void* const* d_in, const int* in_sizes, int n_in,
                              void* d_out, int out_size) {
    (void)in_sizes; (void)n_in; (void)out_size;
    const int*   index     = (const int*)  d_in[0];
    const int*   lab_value = (const int*)  d_in[1];
    const float* alpha     = (const float*)d_in[2];
    const float* h0        = (const float*)d_in[3];
    const float* c0        = (const float*)d_in[4];
    const float* enc       = (const float*)d_in[5];
    const float* lab_table = (const float*)d_in[6];
    const float* W_all     = (const float*)d_in[7];
    const float* b_all     = (const float*)d_in[8];
    const float* W3        = (const float*)d_in[9];
    const float* b3        = (const float*)d_in[10];
    const float* W_eh      = (const float*)d_in[11];
    const float* b_eh      = (const float*)d_in[12];
    const float* W_aw      = (const float*)d_in[13];
    const float* b_aw      = (const float*)d_in[14];
    const float* W_lin     = (const float*)d_in[15];
    const float* b_lin     = (const float*)d_in[16];
    const float* W_ih      = (const float*)d_in[17];
    const float* W_hh      = (const float*)d_in[18];
    const float* b_ih      = (const float*)d_in[19];
    const float* b_hh      = (const float*)d_in[20];
    const float* W_out     = (const float*)d_in[21];
    const float* b_out     = (const float*)d_in[22];
    float* out = (float*)d_out;

    k_emb1   <<<B1 + B_G, 128>>>(lab_value, lab_table, W_all, h0, W_hh);
    k_red1   <<<64, 128>>>();
    k_emb    <<<B_EMB, 128>>>(index, alpha, lab_table, b_all, W3);
    k_vec_emb<<<4, 128>>>(b3);
    k_inp    <<<B_INP, 128>>>(h0, W_eh);
    k_attn   <<<1, 512>>>(b_eh, W_aw, b_aw, enc);
    k_app    <<<B_APP, 128>>>(W_lin);
    k_x      <<<B_X, 128>>>(b_lin, W_lin);
    k_gates  <<<B_G, 512>>>(b_lin, W_ih);
    k_logits <<<B_LG, 128>>>(b_ih, b_hh, c0, W_out, out);
    k_final  <<<1, 512>>>(b_out, out);
}